// round 14
// baseline (speedup 1.0000x reference)
#include <cuda_runtime.h>
#include <cuda_fp16.h>

// ---------------------------------------------------------------------------
// ASymplecticR4_NN: TinyMLP (2->32->32->1) forward + analytic input gradient.
//   out[i] = { x1 + dF/dy1, x2 + dF/dy2, y1, y2 }
//
// Round 12: full fp16 fragment pipeline. mma.sync.m16n8k16 with f16
// accumulators -> MMA outputs are packed f16x2 registers that feed half2
// elementwise math and the next MMA's A-fragment with ZERO cvt instructions.
// b2 rides in MMA1's C operand; x1/x2 ride in MMA3's f32 C operand.
// One warp = two independent 16-element tiles per iteration (ILP2).
// No smem, no barriers, no shuffles.
// ---------------------------------------------------------------------------

#define NTHREADS 128

static __device__ __forceinline__ unsigned packh(float lo, float hi) {
    __half2 h = __floats2half2_rn(lo, hi);
    return *reinterpret_cast<unsigned*>(&h);
}
static __device__ __forceinline__ unsigned bcasth(float v) {
    __half2 h = __float2half2_rn(v);
    return *reinterpret_cast<unsigned*>(&h);
}
static __device__ __forceinline__ __half2 U2H(unsigned u) {
    return *reinterpret_cast<__half2*>(&u);
}
static __device__ __forceinline__ unsigned H2U(__half2 h) {
    return *reinterpret_cast<unsigned*>(&h);
}
static __device__ __forceinline__ unsigned hfma2u(unsigned a, unsigned b, unsigned c) {
    return H2U(__hfma2(U2H(a), U2H(b), U2H(c)));
}
static __device__ __forceinline__ unsigned hmul2u(unsigned a, unsigned b) {
    return H2U(__hmul2(U2H(a), U2H(b)));
}
static __device__ __forceinline__ unsigned hneg2u(unsigned a) {
    return H2U(__hneg2(U2H(a)));
}
static __device__ __forceinline__ unsigned tanh2u(unsigned x) {
    unsigned r;
    asm("tanh.approx.f16x2 %0, %1;" : "=r"(r) : "r"(x));
    return r;
}

// m16n8k16, f16 in / f16 accum. D,C are 2 packed f16x2 regs.
static __device__ __forceinline__ void mma_h(unsigned* d, const unsigned* a,
                                             const unsigned* b, const unsigned* c) {
    asm volatile(
        "mma.sync.aligned.m16n8k16.row.col.f16.f16.f16.f16 "
        "{%0,%1}, {%2,%3,%4,%5}, {%6,%7}, {%8,%9};"
        : "=r"(d[0]), "=r"(d[1])
        : "r"(a[0]), "r"(a[1]), "r"(a[2]), "r"(a[3]),
          "r"(b[0]), "r"(b[1]), "r"(c[0]), "r"(c[1]));
}

// m16n8k16, f16 in / f32 accum (final dY + x).
static __device__ __forceinline__ void mma_f(float* d, const unsigned* a,
                                             const unsigned* b, const float* c) {
    asm volatile(
        "mma.sync.aligned.m16n8k16.row.col.f32.f16.f16.f32 "
        "{%0,%1,%2,%3}, {%4,%5,%6,%7}, {%8,%9}, {%10,%11,%12,%13};"
        : "=f"(d[0]), "=f"(d[1]), "=f"(d[2]), "=f"(d[3])
        : "r"(a[0]), "r"(a[1]), "r"(a[2]), "r"(a[3]),
          "r"(b[0]), "r"(b[1]),
          "f"(c[0]), "f"(c[1]), "f"(c[2]), "f"(c[3]));
}

__global__ void __launch_bounds__(NTHREADS, 5)
mlp_grad_kernel(const float* __restrict__ x1, const float* __restrict__ x2,
                const float* __restrict__ y1, const float* __restrict__ y2,
                const float* __restrict__ W1, const float* __restrict__ b1,
                const float* __restrict__ W2, const float* __restrict__ b2,
                const float* __restrict__ W3, float* __restrict__ out,
                int n, int npairs) {
    const int tid = threadIdx.x;
    const int wid = tid >> 5;
    const int lane = tid & 31;
    const int tg = lane & 3;        // column-pair selector within quad
    const int qr = lane >> 2;       // quad row 0..7

    const unsigned h05 = packh(0.5f, 0.5f);

    // ---- per-thread constants, packed f16x2, fragment layout ----
    // pair j covers cols (8j + 2tg, 8j + 2tg + 1)
    unsigned w10p[4], w11p[4], b1p[4], b2p[4], w3p[4];
#pragma unroll
    for (int j = 0; j < 4; j++) {
        int c0 = 8 * j + 2 * tg;
        w10p[j] = packh(0.5f * W1[c0], 0.5f * W1[c0 + 1]);
        w11p[j] = packh(0.5f * W1[32 + c0], 0.5f * W1[32 + c0 + 1]);
        b1p[j]  = packh(0.5f * b1[c0], 0.5f * b1[c0 + 1]);
        b2p[j]  = packh(0.5f * b2[c0], 0.5f * b2[c0 + 1]);
        w3p[j]  = packh(W3[c0], W3[c0 + 1]);
    }

    // Weight B-fragments (k16n8 col-major): n = 8j+qr, k0 = 16f+2tg.
    // B1 = 0.5*W2 (sigmoid half-scale, exact exponent shift), B2 = W2^T.
    unsigned B1[4][2][2], B2[4][2][2];
#pragma unroll
    for (int j = 0; j < 4; j++) {
#pragma unroll
        for (int f = 0; f < 2; f++) {
            int nn = 8 * j + qr;
            int k0 = 16 * f + 2 * tg;
            B1[j][f][0] = packh(0.5f * W2[k0 * 32 + nn], 0.5f * W2[(k0 + 1) * 32 + nn]);
            B1[j][f][1] = packh(0.5f * W2[(k0 + 8) * 32 + nn], 0.5f * W2[(k0 + 9) * 32 + nn]);
            B2[j][f][0] = packh(W2[nn * 32 + k0], W2[nn * 32 + k0 + 1]);
            B2[j][f][1] = packh(W2[nn * 32 + k0 + 8], W2[nn * 32 + k0 + 9]);
        }
    }
    // B3 = W1^T for MMA3 (dY): n = qr; only n<2 live columns.
    unsigned B3[2][2];
#pragma unroll
    for (int f = 0; f < 2; f++) {
        int k0 = 16 * f + 2 * tg;
        if (qr < 2) {
            B3[f][0] = packh(W1[qr * 32 + k0], W1[qr * 32 + k0 + 1]);
            B3[f][1] = packh(W1[qr * 32 + k0 + 8], W1[qr * 32 + k0 + 9]);
        } else {
            B3[f][0] = 0u;
            B3[f][1] = 0u;
        }
    }

    const int warps_per_cta = NTHREADS / 32;
    const int total_warps = gridDim.x * warps_per_cta;
    const int gw = blockIdx.x * warps_per_cta + wid;

    // --------- single-tile body (clamped tail path) ---------
    auto do_tile_clamped = [&](int base) {
        const int r0 = base + qr;
        const int r1 = base + qr + 8;
        const int r0c = min(r0, n - 1);
        const int r1c = min(r1, n - 1);
        const float vy1a = y1[r0c], vy1b = y1[r1c];
        const float vy2a = y2[r0c], vy2b = y2[r1c];
        const unsigned y1pa = bcasth(vy1a), y2pa = bcasth(vy2a);
        const unsigned y1pb = bcasth(vy1b), y2pb = bcasth(vy2b);

        unsigned h[2][4];
#pragma unroll
        for (int j = 0; j < 4; j++) {
            unsigned p0 = hfma2u(y1pa, w10p[j], hfma2u(y2pa, w11p[j], b1p[j]));
            unsigned p1 = hfma2u(y1pb, w10p[j], hfma2u(y2pb, w11p[j], b1p[j]));
            h[0][j] = hfma2u(tanh2u(p0), h05, h05);
            h[1][j] = hfma2u(tanh2u(p1), h05, h05);
        }
        unsigned a0[4] = {h[0][0], h[1][0], h[0][1], h[1][1]};
        unsigned a1[4] = {h[0][2], h[1][2], h[0][3], h[1][3]};
        unsigned d[4][2];
#pragma unroll
        for (int j = 0; j < 4; j++) {
            unsigned cb[2] = {b2p[j], b2p[j]};
            mma_h(d[j], a0, B1[j][0], cb);
            mma_h(d[j], a1, B1[j][1], d[j]);
        }
        unsigned g[2][4];
#pragma unroll
        for (int j = 0; j < 4; j++) {
#pragma unroll
            for (int s = 0; s < 2; s++) {
                unsigned h2 = hfma2u(tanh2u(d[j][s]), h05, h05);
                unsigned tm = hmul2u(h2, w3p[j]);
                g[s][j] = hfma2u(hneg2u(h2), tm, tm);
            }
        }
        unsigned ga0[4] = {g[0][0], g[1][0], g[0][1], g[1][1]};
        unsigned ga1[4] = {g[0][2], g[1][2], g[0][3], g[1][3]};
        const unsigned cz[2] = {0u, 0u};
#pragma unroll
        for (int j = 0; j < 4; j++) {
            mma_h(d[j], ga0, B2[j][0], cz);
            mma_h(d[j], ga1, B2[j][1], d[j]);
        }
        unsigned dp[2][4];
#pragma unroll
        for (int j = 0; j < 4; j++) {
#pragma unroll
            for (int s = 0; s < 2; s++) {
                unsigned hp = hfma2u(hneg2u(h[s][j]), h[s][j], h[s][j]);
                dp[s][j] = hmul2u(d[j][s], hp);
            }
        }
        unsigned da0[4] = {dp[0][0], dp[1][0], dp[0][1], dp[1][1]};
        unsigned da1[4] = {dp[0][2], dp[1][2], dp[0][3], dp[1][3]};
        float cx[4] = {0.0f, 0.0f, 0.0f, 0.0f};
        if (tg == 0) {
            cx[0] = x1[r0c];
            cx[1] = x2[r0c];
            cx[2] = x1[r1c];
            cx[3] = x2[r1c];
        }
        float d3[4];
        mma_f(d3, da0, B3[0], cx);
        mma_f(d3, da1, B3[1], d3);
        if (tg == 0) {
            if (r0 < n) {
                float4 o;
                o.x = d3[0]; o.y = d3[1]; o.z = vy1a; o.w = vy2a;
                reinterpret_cast<float4*>(out)[r0] = o;
            }
            if (r1 < n) {
                float4 o;
                o.x = d3[2]; o.y = d3[3]; o.z = vy1b; o.w = vy2b;
                reinterpret_cast<float4*>(out)[r1] = o;
            }
        }
    };

    for (int pair = gw; pair < npairs; pair += total_warps) {
        const int base = pair * 32;

        if (base + 32 <= n) {
            // ======= fast path: two independent tiles, stage-interleaved =======
            int r0[2], r1[2];
            float vy1a[2], vy1b[2], vy2a[2], vy2b[2];
#pragma unroll
            for (int t = 0; t < 2; t++) {
                r0[t] = base + 16 * t + qr;
                r1[t] = r0[t] + 8;
                vy1a[t] = y1[r0[t]];
                vy1b[t] = y1[r1[t]];
                vy2a[t] = y2[r0[t]];
                vy2b[t] = y2[r1[t]];
            }

            // ---- layer 1 ----
            unsigned h[2][2][4];
#pragma unroll
            for (int t = 0; t < 2; t++) {
                const unsigned y1pa = bcasth(vy1a[t]);
                const unsigned y2pa = bcasth(vy2a[t]);
                const unsigned y1pb = bcasth(vy1b[t]);
                const unsigned y2pb = bcasth(vy2b[t]);
#pragma unroll
                for (int j = 0; j < 4; j++) {
                    unsigned p0 = hfma2u(y1pa, w10p[j], hfma2u(y2pa, w11p[j], b1p[j]));
                    unsigned p1 = hfma2u(y1pb, w10p[j], hfma2u(y2pb, w11p[j], b1p[j]));
                    h[t][0][j] = hfma2u(tanh2u(p0), h05, h05);
                    h[t][1][j] = hfma2u(tanh2u(p1), h05, h05);
                }
            }

            // ---- MMA1: 0.5*(h1 @ W2) + 0.5*b2 (C operand) ----
            unsigned d[2][4][2];
#pragma unroll
            for (int t = 0; t < 2; t++) {
                unsigned a0[4] = {h[t][0][0], h[t][1][0], h[t][0][1], h[t][1][1]};
                unsigned a1[4] = {h[t][0][2], h[t][1][2], h[t][0][3], h[t][1][3]};
#pragma unroll
                for (int j = 0; j < 4; j++) {
                    unsigned cb[2] = {b2p[j], b2p[j]};
                    mma_h(d[t][j], a0, B1[j][0], cb);
                    mma_h(d[t][j], a1, B1[j][1], d[t][j]);
                }
            }

            // ---- layer 2 elementwise: h2 = sigm; g2 = h2(1-h2)w3 ----
            unsigned g[2][2][4];
#pragma unroll
            for (int t = 0; t < 2; t++) {
#pragma unroll
                for (int j = 0; j < 4; j++) {
#pragma unroll
                    for (int s = 0; s < 2; s++) {
                        unsigned h2 = hfma2u(tanh2u(d[t][j][s]), h05, h05);
                        unsigned tm = hmul2u(h2, w3p[j]);
                        g[t][s][j] = hfma2u(hneg2u(h2), tm, tm);
                    }
                }
            }

            // ---- MMA2: d1 = g2 @ W2^T ----
            const unsigned cz[2] = {0u, 0u};
#pragma unroll
            for (int t = 0; t < 2; t++) {
                unsigned ga0[4] = {g[t][0][0], g[t][1][0], g[t][0][1], g[t][1][1]};
                unsigned ga1[4] = {g[t][0][2], g[t][1][2], g[t][0][3], g[t][1][3]};
#pragma unroll
                for (int j = 0; j < 4; j++) {
                    mma_h(d[t][j], ga0, B2[j][0], cz);
                    mma_h(d[t][j], ga1, B2[j][1], d[t][j]);
                }
            }

            // ---- dp = d1*h1*(1-h1); MMA3 (f32 accum, x seeded); store ----
            float d3[2][4];
#pragma unroll
            for (int t = 0; t < 2; t++) {
                unsigned dp[2][4];
#pragma unroll
                for (int j = 0; j < 4; j++) {
#pragma unroll
                    for (int s = 0; s < 2; s++) {
                        unsigned hp = hfma2u(hneg2u(h[t][s][j]), h[t][s][j], h[t][s][j]);
                        dp[s][j] = hmul2u(d[t][j][s], hp);
                    }
                }
                unsigned da0[4] = {dp[0][0], dp[1][0], dp[0][1], dp[1][1]};
                unsigned da1[4] = {dp[0][2], dp[1][2], dp[0][3], dp[1][3]};
                float cx[4] = {0.0f, 0.0f, 0.0f, 0.0f};
                if (tg == 0) {
                    cx[0] = x1[r0[t]];
                    cx[1] = x2[r0[t]];
                    cx[2] = x1[r1[t]];
                    cx[3] = x2[r1[t]];
                }
                mma_f(d3[t], da0, B3[0], cx);
                mma_f(d3[t], da1, B3[1], d3[t]);
            }

            if (tg == 0) {
#pragma unroll
                for (int t = 0; t < 2; t++) {
                    float4 o;
                    o.x = d3[t][0]; o.y = d3[t][1]; o.z = vy1a[t]; o.w = vy2a[t];
                    reinterpret_cast<float4*>(out)[r0[t]] = o;
                    o.x = d3[t][2]; o.y = d3[t][3]; o.z = vy1b[t]; o.w = vy2b[t];
                    reinterpret_cast<float4*>(out)[r1[t]] = o;
                }
            }
        } else {
            if (base < n) do_tile_clamped(base);
            if (base + 16 < n) do_tile_clamped(base + 16);
        }
    }
}

extern "C" void kernel_launch(void* const* d_in, const int* in_sizes, int n_in,
                              void* d_out, int out_size) {
    const float* x1 = (const float*)d_in[0];
    const float* x2 = (const float*)d_in[1];
    const float* y1 = (const float*)d_in[2];
    const float* y2 = (const float*)d_in[3];
    const float* W1 = (const float*)d_in[4];
    const float* b1 = (const float*)d_in[5];
    const float* W2 = (const float*)d_in[6];
    const float* b2 = (const float*)d_in[7];
    const float* W3 = (const float*)d_in[8];
    float* out = (float*)d_out;

    int n = in_sizes[0];
    int npairs = (n + 31) / 32;

    int per_sm = 0;
    cudaOccupancyMaxActiveBlocksPerMultiprocessor(&per_sm, mlp_grad_kernel,
                                                  NTHREADS, 0);
    if (per_sm < 1) per_sm = 1;
    int sms = 0;
    cudaDeviceGetAttribute(&sms, cudaDevAttrMultiProcessorCount, 0);
    if (sms <= 0) sms = 148;

    int grid = per_sm * sms;
    int max_grid = (npairs + (NTHREADS / 32) - 1) / (NTHREADS / 32);
    if (grid > max_grid) grid = max_grid;

    mlp_grad_kernel<<<grid, NTHREADS>>>(x1, x2, y1, y2, W1, b1, W2, b2, W3, out,
                                        n, npairs);
}

// round 15
// speedup vs baseline: 1.2939x; 1.2939x over previous
#include <cuda_runtime.h>
#include <cuda_fp16.h>

// ---------------------------------------------------------------------------
// ASymplecticR4_NN: TinyMLP (2->32->32->1) forward + analytic input gradient.
//   out[i] = { x1 + dF/dy1, x2 + dF/dy2, y1, y2 }
//
// Round 15: fp16 fragment pipeline (round 14) at 4 CTAs/SM (round 11's
// register budget). Round 14's regression was launch_bounds(128,5) forcing
// regs to 96 -> weight-fragment spills (L1 16->34%, L2 9->24%). Same code
// at a 124-reg budget should be spill-free and keep the instruction-count
// and dependency-chain savings of the f16-accumulator pipeline.
//
// mma.sync.m16n8k16 f16/f16 accum: MMA D-fragments are packed f16x2 regs
// that chain straight into half2 elementwise math and the next MMA's
// A-fragment with zero conversions. b2 rides in MMA1's C operand; x1/x2
// ride in MMA3's f32 C operand (full-precision final sum). One warp = two
// independent 16-element tiles (ILP2). No smem, no barriers, no shuffles.
// ---------------------------------------------------------------------------

#define NTHREADS 128

static __device__ __forceinline__ unsigned packh(float lo, float hi) {
    __half2 h = __floats2half2_rn(lo, hi);
    return *reinterpret_cast<unsigned*>(&h);
}
static __device__ __forceinline__ unsigned bcasth(float v) {
    __half2 h = __float2half2_rn(v);
    return *reinterpret_cast<unsigned*>(&h);
}
static __device__ __forceinline__ __half2 U2H(unsigned u) {
    return *reinterpret_cast<__half2*>(&u);
}
static __device__ __forceinline__ unsigned H2U(__half2 h) {
    return *reinterpret_cast<unsigned*>(&h);
}
static __device__ __forceinline__ unsigned hfma2u(unsigned a, unsigned b, unsigned c) {
    return H2U(__hfma2(U2H(a), U2H(b), U2H(c)));
}
static __device__ __forceinline__ unsigned hmul2u(unsigned a, unsigned b) {
    return H2U(__hmul2(U2H(a), U2H(b)));
}
static __device__ __forceinline__ unsigned hneg2u(unsigned a) {
    return H2U(__hneg2(U2H(a)));
}
static __device__ __forceinline__ unsigned tanh2u(unsigned x) {
    unsigned r;
    asm("tanh.approx.f16x2 %0, %1;" : "=r"(r) : "r"(x));
    return r;
}

// m16n8k16, f16 in / f16 accum. D,C are 2 packed f16x2 regs.
static __device__ __forceinline__ void mma_h(unsigned* d, const unsigned* a,
                                             const unsigned* b, const unsigned* c) {
    asm volatile(
        "mma.sync.aligned.m16n8k16.row.col.f16.f16.f16.f16 "
        "{%0,%1}, {%2,%3,%4,%5}, {%6,%7}, {%8,%9};"
        : "=r"(d[0]), "=r"(d[1])
        : "r"(a[0]), "r"(a[1]), "r"(a[2]), "r"(a[3]),
          "r"(b[0]), "r"(b[1]), "r"(c[0]), "r"(c[1]));
}

// m16n8k16, f16 in / f32 accum (final dY + x).
static __device__ __forceinline__ void mma_f(float* d, const unsigned* a,
                                             const unsigned* b, const float* c) {
    asm volatile(
        "mma.sync.aligned.m16n8k16.row.col.f32.f16.f16.f32 "
        "{%0,%1,%2,%3}, {%4,%5,%6,%7}, {%8,%9}, {%10,%11,%12,%13};"
        : "=f"(d[0]), "=f"(d[1]), "=f"(d[2]), "=f"(d[3])
        : "r"(a[0]), "r"(a[1]), "r"(a[2]), "r"(a[3]),
          "r"(b[0]), "r"(b[1]),
          "f"(c[0]), "f"(c[1]), "f"(c[2]), "f"(c[3]));
}

__global__ void __launch_bounds__(NTHREADS, 4)
mlp_grad_kernel(const float* __restrict__ x1, const float* __restrict__ x2,
                const float* __restrict__ y1, const float* __restrict__ y2,
                const float* __restrict__ W1, const float* __restrict__ b1,
                const float* __restrict__ W2, const float* __restrict__ b2,
                const float* __restrict__ W3, float* __restrict__ out,
                int n, int npairs) {
    const int tid = threadIdx.x;
    const int wid = tid >> 5;
    const int lane = tid & 31;
    const int tg = lane & 3;        // column-pair selector within quad
    const int qr = lane >> 2;       // quad row 0..7

    const unsigned h05 = packh(0.5f, 0.5f);

    // ---- per-thread constants, packed f16x2, fragment layout ----
    // pair j covers cols (8j + 2tg, 8j + 2tg + 1)
    unsigned w10p[4], w11p[4], b1p[4], b2p[4], w3p[4];
#pragma unroll
    for (int j = 0; j < 4; j++) {
        int c0 = 8 * j + 2 * tg;
        w10p[j] = packh(0.5f * W1[c0], 0.5f * W1[c0 + 1]);
        w11p[j] = packh(0.5f * W1[32 + c0], 0.5f * W1[32 + c0 + 1]);
        b1p[j]  = packh(0.5f * b1[c0], 0.5f * b1[c0 + 1]);
        b2p[j]  = packh(0.5f * b2[c0], 0.5f * b2[c0 + 1]);
        w3p[j]  = packh(W3[c0], W3[c0 + 1]);
    }

    // Weight B-fragments (k16n8 col-major): n = 8j+qr, k0 = 16f+2tg.
    // B1 = 0.5*W2 (sigmoid half-scale, exact exponent shift), B2 = W2^T.
    unsigned B1[4][2][2], B2[4][2][2];
#pragma unroll
    for (int j = 0; j < 4; j++) {
#pragma unroll
        for (int f = 0; f < 2; f++) {
            int nn = 8 * j + qr;
            int k0 = 16 * f + 2 * tg;
            B1[j][f][0] = packh(0.5f * W2[k0 * 32 + nn], 0.5f * W2[(k0 + 1) * 32 + nn]);
            B1[j][f][1] = packh(0.5f * W2[(k0 + 8) * 32 + nn], 0.5f * W2[(k0 + 9) * 32 + nn]);
            B2[j][f][0] = packh(W2[nn * 32 + k0], W2[nn * 32 + k0 + 1]);
            B2[j][f][1] = packh(W2[nn * 32 + k0 + 8], W2[nn * 32 + k0 + 9]);
        }
    }
    // B3 = W1^T for MMA3 (dY): n = qr; only n<2 live columns.
    unsigned B3[2][2];
#pragma unroll
    for (int f = 0; f < 2; f++) {
        int k0 = 16 * f + 2 * tg;
        if (qr < 2) {
            B3[f][0] = packh(W1[qr * 32 + k0], W1[qr * 32 + k0 + 1]);
            B3[f][1] = packh(W1[qr * 32 + k0 + 8], W1[qr * 32 + k0 + 9]);
        } else {
            B3[f][0] = 0u;
            B3[f][1] = 0u;
        }
    }

    const int warps_per_cta = NTHREADS / 32;
    const int total_warps = gridDim.x * warps_per_cta;
    const int gw = blockIdx.x * warps_per_cta + wid;

    // --------- single-tile body (clamped tail path) ---------
    auto do_tile_clamped = [&](int base) {
        const int r0 = base + qr;
        const int r1 = base + qr + 8;
        const int r0c = min(r0, n - 1);
        const int r1c = min(r1, n - 1);
        const float vy1a = y1[r0c], vy1b = y1[r1c];
        const float vy2a = y2[r0c], vy2b = y2[r1c];
        const unsigned y1pa = bcasth(vy1a), y2pa = bcasth(vy2a);
        const unsigned y1pb = bcasth(vy1b), y2pb = bcasth(vy2b);

        unsigned h[2][4];
#pragma unroll
        for (int j = 0; j < 4; j++) {
            unsigned p0 = hfma2u(y1pa, w10p[j], hfma2u(y2pa, w11p[j], b1p[j]));
            unsigned p1 = hfma2u(y1pb, w10p[j], hfma2u(y2pb, w11p[j], b1p[j]));
            h[0][j] = hfma2u(tanh2u(p0), h05, h05);
            h[1][j] = hfma2u(tanh2u(p1), h05, h05);
        }
        unsigned a0[4] = {h[0][0], h[1][0], h[0][1], h[1][1]};
        unsigned a1[4] = {h[0][2], h[1][2], h[0][3], h[1][3]};
        unsigned d[4][2];
#pragma unroll
        for (int j = 0; j < 4; j++) {
            unsigned cb[2] = {b2p[j], b2p[j]};
            mma_h(d[j], a0, B1[j][0], cb);
            mma_h(d[j], a1, B1[j][1], d[j]);
        }
        unsigned g[2][4];
#pragma unroll
        for (int j = 0; j < 4; j++) {
#pragma unroll
            for (int s = 0; s < 2; s++) {
                unsigned h2 = hfma2u(tanh2u(d[j][s]), h05, h05);
                unsigned tm = hmul2u(h2, w3p[j]);
                g[s][j] = hfma2u(hneg2u(h2), tm, tm);
            }
        }
        unsigned ga0[4] = {g[0][0], g[1][0], g[0][1], g[1][1]};
        unsigned ga1[4] = {g[0][2], g[1][2], g[0][3], g[1][3]};
        const unsigned cz[2] = {0u, 0u};
#pragma unroll
        for (int j = 0; j < 4; j++) {
            mma_h(d[j], ga0, B2[j][0], cz);
            mma_h(d[j], ga1, B2[j][1], d[j]);
        }
        unsigned dp[2][4];
#pragma unroll
        for (int j = 0; j < 4; j++) {
#pragma unroll
            for (int s = 0; s < 2; s++) {
                unsigned hp = hfma2u(hneg2u(h[s][j]), h[s][j], h[s][j]);
                dp[s][j] = hmul2u(d[j][s], hp);
            }
        }
        unsigned da0[4] = {dp[0][0], dp[1][0], dp[0][1], dp[1][1]};
        unsigned da1[4] = {dp[0][2], dp[1][2], dp[0][3], dp[1][3]};
        float cx[4] = {0.0f, 0.0f, 0.0f, 0.0f};
        if (tg == 0) {
            cx[0] = x1[r0c];
            cx[1] = x2[r0c];
            cx[2] = x1[r1c];
            cx[3] = x2[r1c];
        }
        float d3[4];
        mma_f(d3, da0, B3[0], cx);
        mma_f(d3, da1, B3[1], d3);
        if (tg == 0) {
            if (r0 < n) {
                float4 o;
                o.x = d3[0]; o.y = d3[1]; o.z = vy1a; o.w = vy2a;
                reinterpret_cast<float4*>(out)[r0] = o;
            }
            if (r1 < n) {
                float4 o;
                o.x = d3[2]; o.y = d3[3]; o.z = vy1b; o.w = vy2b;
                reinterpret_cast<float4*>(out)[r1] = o;
            }
        }
    };

    for (int pair = gw; pair < npairs; pair += total_warps) {
        const int base = pair * 32;

        if (base + 32 <= n) {
            // ======= fast path: two independent tiles, stage-interleaved =======
            int r0[2], r1[2];
            float vy1a[2], vy1b[2], vy2a[2], vy2b[2];
#pragma unroll
            for (int t = 0; t < 2; t++) {
                r0[t] = base + 16 * t + qr;
                r1[t] = r0[t] + 8;
                vy1a[t] = y1[r0[t]];
                vy1b[t] = y1[r1[t]];
                vy2a[t] = y2[r0[t]];
                vy2b[t] = y2[r1[t]];
            }

            // ---- layer 1 ----
            unsigned h[2][2][4];
#pragma unroll
            for (int t = 0; t < 2; t++) {
                const unsigned y1pa = bcasth(vy1a[t]);
                const unsigned y2pa = bcasth(vy2a[t]);
                const unsigned y1pb = bcasth(vy1b[t]);
                const unsigned y2pb = bcasth(vy2b[t]);
#pragma unroll
                for (int j = 0; j < 4; j++) {
                    unsigned p0 = hfma2u(y1pa, w10p[j], hfma2u(y2pa, w11p[j], b1p[j]));
                    unsigned p1 = hfma2u(y1pb, w10p[j], hfma2u(y2pb, w11p[j], b1p[j]));
                    h[t][0][j] = hfma2u(tanh2u(p0), h05, h05);
                    h[t][1][j] = hfma2u(tanh2u(p1), h05, h05);
                }
            }

            // ---- MMA1: 0.5*(h1 @ W2) + 0.5*b2 (C operand) ----
            unsigned d[2][4][2];
#pragma unroll
            for (int t = 0; t < 2; t++) {
                unsigned a0[4] = {h[t][0][0], h[t][1][0], h[t][0][1], h[t][1][1]};
                unsigned a1[4] = {h[t][0][2], h[t][1][2], h[t][0][3], h[t][1][3]};
#pragma unroll
                for (int j = 0; j < 4; j++) {
                    unsigned cb[2] = {b2p[j], b2p[j]};
                    mma_h(d[t][j], a0, B1[j][0], cb);
                    mma_h(d[t][j], a1, B1[j][1], d[t][j]);
                }
            }

            // ---- layer 2 elementwise: h2 = sigm; g2 = h2(1-h2)w3 ----
            unsigned g[2][2][4];
#pragma unroll
            for (int t = 0; t < 2; t++) {
#pragma unroll
                for (int j = 0; j < 4; j++) {
#pragma unroll
                    for (int s = 0; s < 2; s++) {
                        unsigned h2 = hfma2u(tanh2u(d[t][j][s]), h05, h05);
                        unsigned tm = hmul2u(h2, w3p[j]);
                        g[t][s][j] = hfma2u(hneg2u(h2), tm, tm);
                    }
                }
            }

            // ---- MMA2: d1 = g2 @ W2^T ----
            const unsigned cz[2] = {0u, 0u};
#pragma unroll
            for (int t = 0; t < 2; t++) {
                unsigned ga0[4] = {g[t][0][0], g[t][1][0], g[t][0][1], g[t][1][1]};
                unsigned ga1[4] = {g[t][0][2], g[t][1][2], g[t][0][3], g[t][1][3]};
#pragma unroll
                for (int j = 0; j < 4; j++) {
                    mma_h(d[t][j], ga0, B2[j][0], cz);
                    mma_h(d[t][j], ga1, B2[j][1], d[t][j]);
                }
            }

            // ---- dp = d1*h1*(1-h1); MMA3 (f32 accum, x seeded); store ----
            float d3[2][4];
#pragma unroll
            for (int t = 0; t < 2; t++) {
                unsigned dp[2][4];
#pragma unroll
                for (int j = 0; j < 4; j++) {
#pragma unroll
                    for (int s = 0; s < 2; s++) {
                        unsigned hp = hfma2u(hneg2u(h[t][s][j]), h[t][s][j], h[t][s][j]);
                        dp[s][j] = hmul2u(d[t][j][s], hp);
                    }
                }
                unsigned da0[4] = {dp[0][0], dp[1][0], dp[0][1], dp[1][1]};
                unsigned da1[4] = {dp[0][2], dp[1][2], dp[0][3], dp[1][3]};
                float cx[4] = {0.0f, 0.0f, 0.0f, 0.0f};
                if (tg == 0) {
                    cx[0] = x1[r0[t]];
                    cx[1] = x2[r0[t]];
                    cx[2] = x1[r1[t]];
                    cx[3] = x2[r1[t]];
                }
                mma_f(d3[t], da0, B3[0], cx);
                mma_f(d3[t], da1, B3[1], d3[t]);
            }

            if (tg == 0) {
#pragma unroll
                for (int t = 0; t < 2; t++) {
                    float4 o;
                    o.x = d3[t][0]; o.y = d3[t][1]; o.z = vy1a[t]; o.w = vy2a[t];
                    reinterpret_cast<float4*>(out)[r0[t]] = o;
                    o.x = d3[t][2]; o.y = d3[t][3]; o.z = vy1b[t]; o.w = vy2b[t];
                    reinterpret_cast<float4*>(out)[r1[t]] = o;
                }
            }
        } else {
            if (base < n) do_tile_clamped(base);
            if (base + 16 < n) do_tile_clamped(base + 16);
        }
    }
}

extern "C" void kernel_launch(void* const* d_in, const int* in_sizes, int n_in,
                              void* d_out, int out_size) {
    const float* x1 = (const float*)d_in[0];
    const float* x2 = (const float*)d_in[1];
    const float* y1 = (const float*)d_in[2];
    const float* y2 = (const float*)d_in[3];
    const float* W1 = (const float*)d_in[4];
    const float* b1 = (const float*)d_in[5];
    const float* W2 = (const float*)d_in[6];
    const float* b2 = (const float*)d_in[7];
    const float* W3 = (const float*)d_in[8];
    float* out = (float*)d_out;

    int n = in_sizes[0];
    int npairs = (n + 31) / 32;

    int per_sm = 0;
    cudaOccupancyMaxActiveBlocksPerMultiprocessor(&per_sm, mlp_grad_kernel,
                                                  NTHREADS, 0);
    if (per_sm < 1) per_sm = 1;
    int sms = 0;
    cudaDeviceGetAttribute(&sms, cudaDevAttrMultiProcessorCount, 0);
    if (sms <= 0) sms = 148;

    int grid = per_sm * sms;
    int max_grid = (npairs + (NTHREADS / 32) - 1) / (NTHREADS / 32);
    if (grid > max_grid) grid = max_grid;

    mlp_grad_kernel<<<grid, NTHREADS>>>(x1, x2, y1, y2, W1, b1, W2, b2, W3, out,
                                        n, npairs);
}

// round 17
// speedup vs baseline: 1.3520x; 1.0449x over previous
#include <cuda_runtime.h>
#include <cuda_fp16.h>

// ---------------------------------------------------------------------------
// ASymplecticR4_NN: TinyMLP (2->32->32->1) forward + analytic input gradient.
//   out[i] = { x1 + dF/dy1, x2 + dF/dy2, y1, y2 }
//
// Round 16: fp16 fragment pipeline (round 15) + weight B-fragments moved to
// a lane-indexed shared-memory table (SoA, conflict-free) to cut ~32
// persistent registers, enabling 5 CTAs/SM under launch_bounds(128,5).
// Also: layer-2 gradient computed directly from tanh (g = 0.25*W3*(1-t^2)),
// skipping the unneeded forward activation h2.
//
// mma.sync.m16n8k16 f16/f16-accum chains register-to-register; b2 rides in
// MMA1's C operand; x1/x2 ride in MMA3's f32 C operand. One warp = two
// independent 16-element tiles (ILP2). No barriers in the loop, no shuffles.
// ---------------------------------------------------------------------------

#define NTHREADS 128

static __device__ __forceinline__ unsigned packh(float lo, float hi) {
    __half2 h = __floats2half2_rn(lo, hi);
    return *reinterpret_cast<unsigned*>(&h);
}
static __device__ __forceinline__ unsigned bcasth(float v) {
    __half2 h = __float2half2_rn(v);
    return *reinterpret_cast<unsigned*>(&h);
}
static __device__ __forceinline__ __half2 U2H(unsigned u) {
    return *reinterpret_cast<__half2*>(&u);
}
static __device__ __forceinline__ unsigned H2U(__half2 h) {
    return *reinterpret_cast<unsigned*>(&h);
}
static __device__ __forceinline__ unsigned hfma2u(unsigned a, unsigned b, unsigned c) {
    return H2U(__hfma2(U2H(a), U2H(b), U2H(c)));
}
static __device__ __forceinline__ unsigned hmul2u(unsigned a, unsigned b) {
    return H2U(__hmul2(U2H(a), U2H(b)));
}
static __device__ __forceinline__ unsigned hneg2u(unsigned a) {
    return H2U(__hneg2(U2H(a)));
}
static __device__ __forceinline__ unsigned tanh2u(unsigned x) {
    unsigned r;
    asm("tanh.approx.f16x2 %0, %1;" : "=r"(r) : "r"(x));
    return r;
}

// m16n8k16, f16 in / f16 accum. D,C are 2 packed f16x2 regs.
static __device__ __forceinline__ void mma_h(unsigned* d, const unsigned* a,
                                             const unsigned* b, const unsigned* c) {
    asm volatile(
        "mma.sync.aligned.m16n8k16.row.col.f16.f16.f16.f16 "
        "{%0,%1}, {%2,%3,%4,%5}, {%6,%7}, {%8,%9};"
        : "=r"(d[0]), "=r"(d[1])
        : "r"(a[0]), "r"(a[1]), "r"(a[2]), "r"(a[3]),
          "r"(b[0]), "r"(b[1]), "r"(c[0]), "r"(c[1]));
}

// m16n8k16, f16 in / f32 accum (final dY + x).
static __device__ __forceinline__ void mma_f(float* d, const unsigned* a,
                                             const unsigned* b, const float* c) {
    asm volatile(
        "mma.sync.aligned.m16n8k16.row.col.f32.f16.f16.f32 "
        "{%0,%1,%2,%3}, {%4,%5,%6,%7}, {%8,%9}, {%10,%11,%12,%13};"
        : "=f"(d[0]), "=f"(d[1]), "=f"(d[2]), "=f"(d[3])
        : "r"(a[0]), "r"(a[1]), "r"(a[2]), "r"(a[3]),
          "r"(b[0]), "r"(b[1]),
          "f"(c[0]), "f"(c[1]), "f"(c[2]), "f"(c[3]));
}

// Shared weight table: entry e for lane l at wtab[e*32 + l].
//   e 0..15  : B1[j][f][k]  (e = j*4 + f*2 + k)   B1 = 0.5*W2 (K-major)
//   e 16..31 : B2[j][f][k]                         B2 = W2^T
//   e 32..35 : B3[f][k]                            B3 = W1^T (rows qr<2)
#define NWENT 36

__global__ void __launch_bounds__(NTHREADS, 5)
mlp_grad_kernel(const float* __restrict__ x1, const float* __restrict__ x2,
                const float* __restrict__ y1, const float* __restrict__ y2,
                const float* __restrict__ W1, const float* __restrict__ b1,
                const float* __restrict__ W2, const float* __restrict__ b2,
                const float* __restrict__ W3, float* __restrict__ out,
                int n, int npairs) {
    __shared__ unsigned wtab[NWENT * 32];

    const int tid = threadIdx.x;
    const int wid = tid >> 5;
    const int lane = tid & 31;
    const int tg = lane & 3;        // column-pair selector within quad
    const int qr = lane >> 2;       // quad row 0..7

    const unsigned h05 = packh(0.5f, 0.5f);

    // ---- build the lane-indexed weight table (one warp's worth of work) ----
    if (tid < 32) {
#pragma unroll
        for (int j = 0; j < 4; j++) {
#pragma unroll
            for (int f = 0; f < 2; f++) {
                int nn = 8 * j + qr;
                int k0 = 16 * f + 2 * tg;
                wtab[(j * 4 + f * 2 + 0) * 32 + lane] =
                    packh(0.5f * W2[k0 * 32 + nn], 0.5f * W2[(k0 + 1) * 32 + nn]);
                wtab[(j * 4 + f * 2 + 1) * 32 + lane] =
                    packh(0.5f * W2[(k0 + 8) * 32 + nn], 0.5f * W2[(k0 + 9) * 32 + nn]);
                wtab[(16 + j * 4 + f * 2 + 0) * 32 + lane] =
                    packh(W2[nn * 32 + k0], W2[nn * 32 + k0 + 1]);
                wtab[(16 + j * 4 + f * 2 + 1) * 32 + lane] =
                    packh(W2[nn * 32 + k0 + 8], W2[nn * 32 + k0 + 9]);
            }
        }
#pragma unroll
        for (int f = 0; f < 2; f++) {
            int k0 = 16 * f + 2 * tg;
            unsigned v0 = 0u, v1 = 0u;
            if (qr < 2) {
                v0 = packh(W1[qr * 32 + k0], W1[qr * 32 + k0 + 1]);
                v1 = packh(W1[qr * 32 + k0 + 8], W1[qr * 32 + k0 + 9]);
            }
            wtab[(32 + f * 2 + 0) * 32 + lane] = v0;
            wtab[(32 + f * 2 + 1) * 32 + lane] = v1;
        }
    }

    // ---- per-thread constants in registers (hot in every chain) ----
    unsigned w10p[4], w11p[4], b1p[4], b2p[4], w3q[4];
#pragma unroll
    for (int j = 0; j < 4; j++) {
        int c0 = 8 * j + 2 * tg;
        w10p[j] = packh(0.5f * W1[c0], 0.5f * W1[c0 + 1]);
        w11p[j] = packh(0.5f * W1[32 + c0], 0.5f * W1[32 + c0 + 1]);
        b1p[j]  = packh(0.5f * b1[c0], 0.5f * b1[c0 + 1]);
        b2p[j]  = packh(0.5f * b2[c0], 0.5f * b2[c0 + 1]);
        w3q[j]  = packh(0.25f * W3[c0], 0.25f * W3[c0 + 1]);
    }

    __syncthreads();
    const unsigned* tab = &wtab[lane];

    const int warps_per_cta = NTHREADS / 32;
    const int total_warps = gridDim.x * warps_per_cta;
    const int gw = blockIdx.x * warps_per_cta + wid;

    // --------- single-tile body (clamped tail path) ---------
    auto do_tile_clamped = [&](int base) {
        const int r0 = base + qr;
        const int r1 = base + qr + 8;
        const int r0c = min(r0, n - 1);
        const int r1c = min(r1, n - 1);
        const float vy1a = y1[r0c], vy1b = y1[r1c];
        const float vy2a = y2[r0c], vy2b = y2[r1c];
        const unsigned y1pa = bcasth(vy1a), y2pa = bcasth(vy2a);
        const unsigned y1pb = bcasth(vy1b), y2pb = bcasth(vy2b);

        unsigned h[2][4];
#pragma unroll
        for (int j = 0; j < 4; j++) {
            unsigned p0 = hfma2u(y1pa, w10p[j], hfma2u(y2pa, w11p[j], b1p[j]));
            unsigned p1 = hfma2u(y1pb, w10p[j], hfma2u(y2pb, w11p[j], b1p[j]));
            h[0][j] = hfma2u(tanh2u(p0), h05, h05);
            h[1][j] = hfma2u(tanh2u(p1), h05, h05);
        }
        unsigned a0[4] = {h[0][0], h[1][0], h[0][1], h[1][1]};
        unsigned a1[4] = {h[0][2], h[1][2], h[0][3], h[1][3]};
        unsigned d[4][2];
#pragma unroll
        for (int j = 0; j < 4; j++) {
            unsigned b0[2] = {tab[(j * 4 + 0) * 32], tab[(j * 4 + 1) * 32]};
            unsigned b1f[2] = {tab[(j * 4 + 2) * 32], tab[(j * 4 + 3) * 32]};
            unsigned cb[2] = {b2p[j], b2p[j]};
            mma_h(d[j], a0, b0, cb);
            mma_h(d[j], a1, b1f, d[j]);
        }
        unsigned g[2][4];
#pragma unroll
        for (int j = 0; j < 4; j++) {
#pragma unroll
            for (int s = 0; s < 2; s++) {
                unsigned t2 = tanh2u(d[j][s]);
                unsigned tsq = hmul2u(t2, t2);
                g[s][j] = hfma2u(hneg2u(tsq), w3q[j], w3q[j]);
            }
        }
        unsigned ga0[4] = {g[0][0], g[1][0], g[0][1], g[1][1]};
        unsigned ga1[4] = {g[0][2], g[1][2], g[0][3], g[1][3]};
        const unsigned cz[2] = {0u, 0u};
#pragma unroll
        for (int j = 0; j < 4; j++) {
            unsigned b0[2] = {tab[(16 + j * 4 + 0) * 32], tab[(16 + j * 4 + 1) * 32]};
            unsigned b1f[2] = {tab[(16 + j * 4 + 2) * 32], tab[(16 + j * 4 + 3) * 32]};
            mma_h(d[j], ga0, b0, cz);
            mma_h(d[j], ga1, b1f, d[j]);
        }
        unsigned dp[2][4];
#pragma unroll
        for (int j = 0; j < 4; j++) {
#pragma unroll
            for (int s = 0; s < 2; s++) {
                unsigned hp = hfma2u(hneg2u(h[s][j]), h[s][j], h[s][j]);
                dp[s][j] = hmul2u(d[j][s], hp);
            }
        }
        unsigned da0[4] = {dp[0][0], dp[1][0], dp[0][1], dp[1][1]};
        unsigned da1[4] = {dp[0][2], dp[1][2], dp[0][3], dp[1][3]};
        unsigned b30[2] = {tab[(32 + 0) * 32], tab[(32 + 1) * 32]};
        unsigned b31[2] = {tab[(32 + 2) * 32], tab[(32 + 3) * 32]};
        float cx[4] = {0.0f, 0.0f, 0.0f, 0.0f};
        if (tg == 0) {
            cx[0] = x1[r0c];
            cx[1] = x2[r0c];
            cx[2] = x1[r1c];
            cx[3] = x2[r1c];
        }
        float d3[4];
        mma_f(d3, da0, b30, cx);
        mma_f(d3, da1, b31, d3);
        if (tg == 0) {
            if (r0 < n) {
                float4 o;
                o.x = d3[0]; o.y = d3[1]; o.z = vy1a; o.w = vy2a;
                reinterpret_cast<float4*>(out)[r0] = o;
            }
            if (r1 < n) {
                float4 o;
                o.x = d3[2]; o.y = d3[3]; o.z = vy1b; o.w = vy2b;
                reinterpret_cast<float4*>(out)[r1] = o;
            }
        }
    };

    for (int pair = gw; pair < npairs; pair += total_warps) {
        const int base = pair * 32;

        if (base + 32 <= n) {
            // ======= fast path: two independent tiles, stage-interleaved =======
            int r0[2], r1[2];
            float vy1a[2], vy1b[2], vy2a[2], vy2b[2];
#pragma unroll
            for (int t = 0; t < 2; t++) {
                r0[t] = base + 16 * t + qr;
                r1[t] = r0[t] + 8;
                vy1a[t] = y1[r0[t]];
                vy1b[t] = y1[r1[t]];
                vy2a[t] = y2[r0[t]];
                vy2b[t] = y2[r1[t]];
            }

            // ---- layer 1 ----
            unsigned h[2][2][4];
#pragma unroll
            for (int t = 0; t < 2; t++) {
                const unsigned y1pa = bcasth(vy1a[t]);
                const unsigned y2pa = bcasth(vy2a[t]);
                const unsigned y1pb = bcasth(vy1b[t]);
                const unsigned y2pb = bcasth(vy2b[t]);
#pragma unroll
                for (int j = 0; j < 4; j++) {
                    unsigned p0 = hfma2u(y1pa, w10p[j], hfma2u(y2pa, w11p[j], b1p[j]));
                    unsigned p1 = hfma2u(y1pb, w10p[j], hfma2u(y2pb, w11p[j], b1p[j]));
                    h[t][0][j] = hfma2u(tanh2u(p0), h05, h05);
                    h[t][1][j] = hfma2u(tanh2u(p1), h05, h05);
                }
            }

            // ---- MMA1: 0.5*(h1 @ W2) + 0.5*b2; B loaded from smem, shared t ----
            unsigned a0[2][4], a1[2][4];
#pragma unroll
            for (int t = 0; t < 2; t++) {
                a0[t][0] = h[t][0][0]; a0[t][1] = h[t][1][0];
                a0[t][2] = h[t][0][1]; a0[t][3] = h[t][1][1];
                a1[t][0] = h[t][0][2]; a1[t][1] = h[t][1][2];
                a1[t][2] = h[t][0][3]; a1[t][3] = h[t][1][3];
            }
            unsigned d[2][4][2];
#pragma unroll
            for (int j = 0; j < 4; j++) {
                unsigned b0[2] = {tab[(j * 4 + 0) * 32], tab[(j * 4 + 1) * 32]};
                unsigned b1f[2] = {tab[(j * 4 + 2) * 32], tab[(j * 4 + 3) * 32]};
                unsigned cb[2] = {b2p[j], b2p[j]};
#pragma unroll
                for (int t = 0; t < 2; t++) {
                    mma_h(d[t][j], a0[t], b0, cb);
                    mma_h(d[t][j], a1[t], b1f, d[t][j]);
                }
            }

            // ---- layer 2 gradient: g = 0.25*W3*(1 - tanh^2(pre2/2)) ----
            unsigned g[2][2][4];
#pragma unroll
            for (int t = 0; t < 2; t++) {
#pragma unroll
                for (int j = 0; j < 4; j++) {
#pragma unroll
                    for (int s = 0; s < 2; s++) {
                        unsigned t2 = tanh2u(d[t][j][s]);
                        unsigned tsq = hmul2u(t2, t2);
                        g[t][s][j] = hfma2u(hneg2u(tsq), w3q[j], w3q[j]);
                    }
                }
            }

            // ---- MMA2: d1 = g2 @ W2^T ----
            const unsigned cz[2] = {0u, 0u};
            unsigned ga0[2][4], ga1[2][4];
#pragma unroll
            for (int t = 0; t < 2; t++) {
                ga0[t][0] = g[t][0][0]; ga0[t][1] = g[t][1][0];
                ga0[t][2] = g[t][0][1]; ga0[t][3] = g[t][1][1];
                ga1[t][0] = g[t][0][2]; ga1[t][1] = g[t][1][2];
                ga1[t][2] = g[t][0][3]; ga1[t][3] = g[t][1][3];
            }
#pragma unroll
            for (int j = 0; j < 4; j++) {
                unsigned b0[2] = {tab[(16 + j * 4 + 0) * 32], tab[(16 + j * 4 + 1) * 32]};
                unsigned b1f[2] = {tab[(16 + j * 4 + 2) * 32], tab[(16 + j * 4 + 3) * 32]};
#pragma unroll
                for (int t = 0; t < 2; t++) {
                    mma_h(d[t][j], ga0[t], b0, cz);
                    mma_h(d[t][j], ga1[t], b1f, d[t][j]);
                }
            }

            // ---- dp = d1*h1*(1-h1); MMA3 (f32 accum, x seeded); store ----
            unsigned b30[2] = {tab[(32 + 0) * 32], tab[(32 + 1) * 32]};
            unsigned b31[2] = {tab[(32 + 2) * 32], tab[(32 + 3) * 32]};
            float d3[2][4];
#pragma unroll
            for (int t = 0; t < 2; t++) {
                unsigned dp[2][4];
#pragma unroll
                for (int j = 0; j < 4; j++) {
#pragma unroll
                    for (int s = 0; s < 2; s++) {
                        unsigned hp = hfma2u(hneg2u(h[t][s][j]), h[t][s][j], h[t][s][j]);
                        dp[s][j] = hmul2u(d[t][j][s], hp);
                    }
                }
                unsigned da0[4] = {dp[0][0], dp[1][0], dp[0][1], dp[1][1]};
                unsigned da1[4] = {dp[0][2], dp[1][2], dp[0][3], dp[1][3]};
                float cx[4] = {0.0f, 0.0f, 0.0f, 0.0f};
                if (tg == 0) {
                    cx[0] = x1[r0[t]];
                    cx[1] = x2[r0[t]];
                    cx[2] = x1[r1[t]];
                    cx[3] = x2[r1[t]];
                }
                mma_f(d3[t], da0, b30, cx);
                mma_f(d3[t], da1, b31, d3[t]);
            }

            if (tg == 0) {
#pragma unroll
                for (int t = 0; t < 2; t++) {
                    float4 o;
                    o.x = d3[t][0]; o.y = d3[t][1]; o.z = vy1a[t]; o.w = vy2a[t];
                    reinterpret_cast<float4*>(out)[r0[t]] = o;
                    o.x = d3[t][2]; o.y = d3[t][3]; o.z = vy1b[t]; o.w = vy2b[t];
                    reinterpret_cast<float4*>(out)[r1[t]] = o;
                }
            }
        } else {
            if (base < n) do_tile_clamped(base);
            if (base + 16 < n) do_tile_clamped(base + 16);
        }
    }
}

extern "C" void kernel_launch(void* const* d_in, const int* in_sizes, int n_in,
                              void* d_out, int out_size) {
    const float* x1 = (const float*)d_in[0];
    const float* x2 = (const float*)d_in[1];
    const float* y1 = (const float*)d_in[2];
    const float* y2 = (const float*)d_in[3];
    const float* W1 = (const float*)d_in[4];
    const float* b1 = (const float*)d_in[5];
    const float* W2 = (const float*)d_in[6];
    const float* b2 = (const float*)d_in[7];
    const float* W3 = (const float*)d_in[8];
    float* out = (float*)d_out;

    int n = in_sizes[0];
    int npairs = (n + 31) / 32;

    int per_sm = 0;
    cudaOccupancyMaxActiveBlocksPerMultiprocessor(&per_sm, mlp_grad_kernel,
                                                  NTHREADS, 0);
    if (per_sm < 1) per_sm = 1;
    int sms = 0;
    cudaDeviceGetAttribute(&sms, cudaDevAttrMultiProcessorCount, 0);
    if (sms <= 0) sms = 148;

    int grid = per_sm * sms;
    int max_grid = (npairs + (NTHREADS / 32) - 1) / (NTHREADS / 32);
    if (grid > max_grid) grid = max_grid;

    mlp_grad_kernel<<<grid, NTHREADS>>>(x1, x2, y1, y2, W1, b1, W2, b2, W3, out,
                                        n, npairs);
}